// round 16
// baseline (speedup 1.0000x reference)
#include <cuda_runtime.h>
#include <math_constants.h>

// WeightedChamferDistance: B=4, N=M=8192, D=3.
// out = mean_b( sum_n min_m d2 * w[b,n] ) + mean_b( sum_m min_n d2 )
//
// Champion pass1 (R4 config, 73.4 us) + fused epilogue:
// Pass1: 2048 blocks; each block = 512 points (4/thread, 128 threads) x one
//        512-other chunk. Others preprocessed in shared as packed pairs
//        (-2x,-2y,-2z,|o|^2); fma.rn.f32x2 = 2 others/instr; next iter's
//        LDS.128 pair register-prefetched.
// Pass2 (fused): min over 16 split-partials, weight fwd direction, block
//        reduce; LAST block (atomicInc ticket, self-wrapping to 0 for graph
//        replay) re-reduces the 256 partial sums and writes the output.
//        Deterministic: g_sums contents and final fixed-order sum are
//        independent of block completion order.

#define BATCH   4
#define NPTS    8192
#define TILE    512             // others per chunk (8 KB tile)
#define SPLITS  16              // NPTS / TILE
#define T1      128             // pass1 threads (4 points each)
#define PPB     512             // points per block

__device__ float g_partial[2 * BATCH * NPTS * SPLITS];  // 4 MB
__device__ float g_sums[256];
__device__ unsigned int g_done;     // zero-initialized; self-resets via wrap

__global__ __launch_bounds__(T1, 8)
void chamfer_pass1(const float* __restrict__ src,
                   const float* __restrict__ tgt)
{
    // Tile layout per pair k (8 floats = 32 B):
    //  [0]=-2x0 [1]=-2x1 [2]=-2y0 [3]=-2y1 [4]=-2z0 [5]=-2z1 [6]=o2_0 [7]=o2_1
    __shared__ float s_tile[TILE * 4 + 8];   // +8 floats: prefetch overread pad

    const int bx    = blockIdx.x;
    const int split = bx & (SPLITS - 1);
    const int g     = bx >> 4;                       // 0..127 point-group id
    const bool bwd  = g >= (BATCH * (NPTS / PPB));   // >= 64
    const int lg    = g & 63;
    const int b     = lg >> 4;
    const int pg    = lg & 15;

    const float* pts = bwd ? tgt : src;
    const float* oth = bwd ? src : tgt;

    const int pid0 = pg * PPB + threadIdx.x;         // +0,+128,+256,+384

    // Load this thread's four points; duplicate coords into packed operands
    unsigned long long cx[4], cy[4], cz[4];
    float p2[4];
    #pragma unroll
    for (int k = 0; k < 4; ++k) {
        const float* p = pts + ((size_t)b * NPTS + pid0 + k * T1) * 3;
        const float x = p[0], y = p[1], z = p[2];
        p2[k] = x * x + y * y + z * z;
        asm("mov.b64 %0,{%1,%1};" : "=l"(cx[k]) : "f"(x));
        asm("mov.b64 %0,{%1,%1};" : "=l"(cy[k]) : "f"(y));
        asm("mov.b64 %0,{%1,%1};" : "=l"(cz[k]) : "f"(z));
    }

    unsigned sbase;
    asm("{ .reg .u64 t; cvta.to.shared.u64 t, %1; cvt.u32.u64 %0, t; }"
        : "=r"(sbase) : "l"(s_tile));

    // Cooperative tile load + preprocess for this chunk
    const float* obase = oth + ((size_t)b * NPTS + split * TILE) * 3;
    #pragma unroll
    for (int it = 0; it < TILE / T1; ++it) {
        const int idx = it * T1 + threadIdx.x;
        const float* o = obase + (size_t)idx * 3;
        const float ox = o[0], oy = o[1], oz = o[2];
        const float o2 = ox * ox + oy * oy + oz * oz;
        float* bp = s_tile + (idx >> 1) * 8 + (idx & 1);
        bp[0] = -2.0f * ox;
        bp[2] = -2.0f * oy;
        bp[4] = -2.0f * oz;
        bp[6] = o2;
    }
    __syncthreads();

    float m0[4], m1[4];
    #pragma unroll
    for (int k = 0; k < 4; ++k) { m0[k] = CUDART_INF_F; m1[k] = CUDART_INF_F; }

    // Scan with register prefetch: iter kk computes on (txp..t2p) while
    // (ntx..nt2) for kk+1 is in flight. Last iter overreads into the pad.
    unsigned long long txp, typ, tzp, t2p;
    asm("ld.shared.v2.u64 {%0,%1},[%2];" : "=l"(txp), "=l"(typ) : "r"(sbase));
    asm("ld.shared.v2.u64 {%0,%1},[%2];" : "=l"(tzp), "=l"(t2p) : "r"(sbase + 16u));

    #pragma unroll 8
    for (int kk = 0; kk < TILE / 2; ++kk) {
        const unsigned a = sbase + kk * 32u + 32u;
        unsigned long long ntx, nty, ntz, nt2;
        asm("ld.shared.v2.u64 {%0,%1},[%2];" : "=l"(ntx), "=l"(nty) : "r"(a));
        asm("ld.shared.v2.u64 {%0,%1},[%2];" : "=l"(ntz), "=l"(nt2) : "r"(a + 16u));
        #pragma unroll
        for (int k = 0; k < 4; ++k) {
            unsigned long long acc;
            asm("fma.rn.f32x2 %0,%1,%2,%3;" : "=l"(acc) : "l"(cx[k]), "l"(txp), "l"(t2p));
            asm("fma.rn.f32x2 %0,%1,%2,%3;" : "=l"(acc) : "l"(cy[k]), "l"(typ), "l"(acc));
            asm("fma.rn.f32x2 %0,%1,%2,%3;" : "=l"(acc) : "l"(cz[k]), "l"(tzp), "l"(acc));
            float lo, hi;
            asm("mov.b64 {%0,%1},%2;" : "=f"(lo), "=f"(hi) : "l"(acc));
            m0[k] = fminf(m0[k], lo);
            m1[k] = fminf(m1[k], hi);
        }
        txp = ntx; typ = nty; tzp = ntz; t2p = nt2;
    }

    const int base = ((int)bwd * BATCH + b) * NPTS;
    #pragma unroll
    for (int k = 0; k < 4; ++k) {
        g_partial[(size_t)(base + pid0 + k * T1) * SPLITS + split] =
            p2[k] + fminf(m0[k], m1[k]);
    }
}

__global__ __launch_bounds__(256)
void chamfer_pass2(const float* __restrict__ w, float* __restrict__ out)
{
    __shared__ float s_red[256];
    __shared__ bool s_last;

    const int q = blockIdx.x * 256 + threadIdx.x;   // 0 .. 65535
    const int bwd = q >> 15;                        // 0 = fwd (weighted)
    const int r   = q & 32767;
    const int b   = r >> 13;
    const int pid = r & (NPTS - 1);

    const float4* pp = (const float4*)(g_partial + (size_t)q * SPLITS);
    float m = CUDART_INF_F;
    #pragma unroll
    for (int i = 0; i < SPLITS / 4; ++i) {
        const float4 v = pp[i];
        m = fminf(m, fminf(fminf(v.x, v.y), fminf(v.z, v.w)));
    }
    if (!bwd) m *= w[(size_t)b * NPTS + pid];

    s_red[threadIdx.x] = m;
    __syncthreads();
    #pragma unroll
    for (int s = 128; s > 0; s >>= 1) {
        if (threadIdx.x < s) s_red[threadIdx.x] += s_red[threadIdx.x + s];
        __syncthreads();
    }
    if (threadIdx.x == 0) {
        g_sums[blockIdx.x] = s_red[0];
        __threadfence();
        // atomicInc wraps 255 -> 0, so the counter self-resets for the
        // next graph replay; 'true' exactly for the 256th (last) block.
        s_last = (atomicInc(&g_done, 255u) == 255u);
    }
    __syncthreads();

    if (s_last) {
        // Last block: g_sums fully visible (threadfence + atomic order).
        s_red[threadIdx.x] = g_sums[threadIdx.x];
        __syncthreads();
        #pragma unroll
        for (int s = 128; s > 0; s >>= 1) {
            if (threadIdx.x < s) s_red[threadIdx.x] += s_red[threadIdx.x + s];
            __syncthreads();
        }
        if (threadIdx.x == 0) out[0] = s_red[0] * (1.0f / (float)BATCH);
    }
}

extern "C" void kernel_launch(void* const* d_in, const int* in_sizes, int n_in,
                              void* d_out, int out_size)
{
    const float* src = (const float*)d_in[0];   // [B, N, 3]
    const float* tgt = (const float*)d_in[1];   // [B, M, 3]
    const float* w   = (const float*)d_in[2];   // [B, N]
    float* out = (float*)d_out;

    // 2 dirs * 4 batches * 16 point-groups * 16 splits = 2048 blocks
    chamfer_pass1<<<2 * BATCH * (NPTS / PPB) * SPLITS, T1>>>(src, tgt);
    chamfer_pass2<<<256, 256>>>(w, out);
}